// round 7
// baseline (speedup 1.0000x reference)
#include <cuda_runtime.h>
#include <cuda_bf16.h>
#include <cstdint>
#include <cstddef>

// ---------------------------------------------------------------------------
// Problem dims (fixed by the dataset)
// ---------------------------------------------------------------------------
#define MDIM 8192
#define NDIM 4096
#define KDIM 4096

#define BM 128
#define BN 128
#define BK 64
#define NSTAGE 3
#define NIT (KDIM / BK)          // 64
#define PITCH 144                // 128B data + 16B pad: conflict-free ldsm
#define A_STAGE_BYTES (128 * PITCH)            // 18432
#define STAGE_BYTES   (2 * A_STAGE_BYTES)      // 36864 (A + B)
#define SMEM_DATA_OFF 1024
#define SMEM_BYTES (SMEM_DATA_OFF + NSTAGE * STAGE_BYTES)   // 111616
#define STAGE_TX 32768           // bytes of payload per stage (A+B, data only)

// ---------------------------------------------------------------------------
// Scratch (device globals: the sanctioned no-alloc workaround)
// ---------------------------------------------------------------------------
__device__ __nv_bfloat16 g_A[(size_t)MDIM * KDIM];   // x as bf16, [M,K] row-major
__device__ __nv_bfloat16 g_Wt[(size_t)NDIM * KDIM];  // dequant W^T, [N,K] row-major

__constant__ float c_nf4[16] = {
    -1.0f, -0.6961928009986877f, -0.5250730514526367f, -0.39491748809814453f,
    -0.28444138169288635f, -0.18477343022823334f, -0.09105003625154495f, 0.0f,
    0.07958029955625534f, 0.16093020141124725f, 0.24611230194568634f,
    0.33791524171829224f, 0.44070982933044434f, 0.5626170039176941f,
    0.7229568362236023f, 1.0f };

// ---------------------------------------------------------------------------
// PTX helpers (baseline sm_80/sm_90 features only — NO 'a'-suffix features)
// ---------------------------------------------------------------------------
static __device__ __forceinline__ uint32_t s2u(const void* p) {
    uint32_t a;
    asm("{ .reg .u64 t; cvta.to.shared.u64 t, %1; cvt.u32.u64 %0, t; }"
        : "=r"(a) : "l"(p));
    return a;
}
static __device__ __forceinline__ void mbar_init(uint32_t a, uint32_t cnt) {
    asm volatile("mbarrier.init.shared.b64 [%0], %1;" :: "r"(a), "r"(cnt) : "memory");
}
static __device__ __forceinline__ void mbar_expect_tx(uint32_t a, uint32_t tx) {
    asm volatile("mbarrier.arrive.expect_tx.shared.b64 _, [%0], %1;"
                 :: "r"(a), "r"(tx) : "memory");
}
static __device__ __forceinline__ void mbar_wait(uint32_t a, uint32_t parity) {
    asm volatile(
        "{\n\t.reg .pred P;\n"
        "LW%=:\n\t"
        "mbarrier.try_wait.parity.acquire.cta.shared::cta.b64 P, [%0], %1, 0x989680;\n\t"
        "@P bra LD%=;\n\t"
        "bra LW%=;\n"
        "LD%=:\n\t}"
        :: "r"(a), "r"(parity) : "memory");
}
// Bulk async copy: 128 contiguous bytes gmem -> smem, completion -> mbarrier tx.
static __device__ __forceinline__ void bulk128(uint32_t dst, const void* src,
                                               uint32_t mbar) {
    asm volatile(
        "cp.async.bulk.shared::cta.global.mbarrier::complete_tx::bytes "
        "[%0], [%1], 128, [%2];"
        :: "r"(dst), "l"(src), "r"(mbar) : "memory");
}
static __device__ __forceinline__ void ldsm_x4(uint32_t* r, uint32_t addr) {
    asm volatile("ldmatrix.sync.aligned.m8n8.x4.shared.b16 {%0,%1,%2,%3}, [%4];"
                 : "=r"(r[0]), "=r"(r[1]), "=r"(r[2]), "=r"(r[3])
                 : "r"(addr));
}
static __device__ __forceinline__ void mma_bf16(
    float* d, const uint32_t* a, const uint32_t* b)
{
    asm volatile(
        "mma.sync.aligned.m16n8k16.row.col.f32.bf16.bf16.f32 "
        "{%0,%1,%2,%3}, {%4,%5,%6,%7}, {%8,%9}, {%0,%1,%2,%3};"
        : "+f"(d[0]), "+f"(d[1]), "+f"(d[2]), "+f"(d[3])
        : "r"(a[0]), "r"(a[1]), "r"(a[2]), "r"(a[3]), "r"(b[0]), "r"(b[1]));
}

// ---------------------------------------------------------------------------
// Kernel 1: x (fp32) -> g_A (bf16)
// ---------------------------------------------------------------------------
__global__ void __launch_bounds__(256) convx_kernel(const float* __restrict__ x)
{
    size_t i = ((size_t)blockIdx.x * 256 + threadIdx.x) * 8;
    float4 a = *reinterpret_cast<const float4*>(x + i);
    float4 b = *reinterpret_cast<const float4*>(x + i + 4);
    __nv_bfloat162 h0 = __floats2bfloat162_rn(a.x, a.y);
    __nv_bfloat162 h1 = __floats2bfloat162_rn(a.z, a.w);
    __nv_bfloat162 h2 = __floats2bfloat162_rn(b.x, b.y);
    __nv_bfloat162 h3 = __floats2bfloat162_rn(b.z, b.w);
    uint4 u;
    u.x = *reinterpret_cast<unsigned*>(&h0);
    u.y = *reinterpret_cast<unsigned*>(&h1);
    u.z = *reinterpret_cast<unsigned*>(&h2);
    u.w = *reinterpret_cast<unsigned*>(&h3);
    *reinterpret_cast<uint4*>(&g_A[i]) = u;
}

// ---------------------------------------------------------------------------
// Kernel 2: NF4 dequant + transpose: qweight (int32 [K/8, N]) -> g_Wt (bf16 [N, K])
// ---------------------------------------------------------------------------
__global__ void __launch_bounds__(256) dequant_kernel(
    const int* __restrict__ qw, const float* __restrict__ sc)
{
    int idx = blockIdx.x * 256 + threadIdx.x;    // 0 .. N*512-1
    int n = idx >> 9;                            // output column (0..4095)
    int r = idx & 511;                           // int32 row (k = 8r + j)
    unsigned q = (unsigned)qw[(size_t)r * NDIM + n];
    float s = sc[(size_t)(r >> 4) * NDIM + n];   // group = 8r/128 = r/16
    unsigned w[4];
#pragma unroll
    for (int jj = 0; jj < 4; jj++) {
        float f0 = c_nf4[(q >> (8 * jj)) & 15] * s;
        float f1 = c_nf4[(q >> (8 * jj + 4)) & 15] * s;
        __nv_bfloat162 h = __floats2bfloat162_rn(f0, f1);
        w[jj] = *reinterpret_cast<unsigned*>(&h);
    }
    uint4 u; u.x = w[0]; u.y = w[1]; u.z = w[2]; u.w = w[3];
    *reinterpret_cast<uint4*>(&g_Wt[(size_t)n * KDIM + r * 8]) = u;
}

// ---------------------------------------------------------------------------
// Kernel 3: GEMM  out[M,N] = g_A[M,K] @ g_Wt[N,K]^T + bias
//   128x128 CTA tile, 4 warps 2x2, warp tile 64x64, 3-stage pipeline filled by
//   cp.async.bulk (2 x 128B per thread per chunk) + mbarrier expect_tx/parity.
//   Smem rows padded to 144B: ldsm row-bank stride 36 ≡ 4 -> conflict-free
//   without swizzle. Fragments register double-buffered (R6 schedule).
// ---------------------------------------------------------------------------
__global__ void __launch_bounds__(128, 2) gemm_kernel(
    float* __restrict__ out, const float* __restrict__ bias)
{
    extern __shared__ char smem[];
    const uint32_t sb = s2u(smem);
    const int tid = threadIdx.x;
    const int wid = tid >> 5, lane = tid & 31;
    const int wm = wid >> 1, wn = wid & 1;        // warp grid 2 (M) x 2 (N)
    const int bm = blockIdx.y * BM, bn = blockIdx.x * BN;

    if (tid == 0) {
        mbar_init(sb + 0, 1);
        mbar_init(sb + 8, 1);
        mbar_init(sb + 16, 1);
    }
    __syncthreads();

    // Per-thread global row pointers (thread t owns A row t and B row t).
    const char* Arow = (const char*)(g_A  + (size_t)(bm + tid) * KDIM);
    const char* Brow = (const char*)(g_Wt + (size_t)(bn + tid) * KDIM);
    const uint32_t dA = sb + SMEM_DATA_OFF + (uint32_t)tid * PITCH;

    // Issue this thread's 2 bulk copies for chunk kc into stage s.
    auto issue_loads = [&](int s, int kc) {
        uint32_t mb = sb + 8u * (uint32_t)s;
        uint32_t da = dA + (uint32_t)s * STAGE_BYTES;
        bulk128(da, Arow + (size_t)kc * 128, mb);
        bulk128(da + A_STAGE_BYTES, Brow + (size_t)kc * 128, mb);
    };

    // Prologue: stages 0,1
    if (tid == 0) { mbar_expect_tx(sb + 0, STAGE_TX); mbar_expect_tx(sb + 8, STAGE_TX); }
    issue_loads(0, 0);
    issue_loads(1, 1);

    float acc[4][8][4];
#pragma unroll
    for (int mi = 0; mi < 4; mi++)
#pragma unroll
        for (int ni = 0; ni < 8; ni++)
#pragma unroll
            for (int j = 0; j < 4; j++) acc[mi][ni][j] = 0.0f;

    // Per-thread ldmatrix offsets (stage-relative, pitch 144, no swizzle).
    const int a_row = wm * 64 + (lane & 15);                      // + mi*16
    const int a_kb  = ((lane >> 4) & 1) * 16;                     // + ks*32
    const int b_row = wn * 64 + (lane & 7) + ((lane >> 4) << 3);  // + nh*16
    const int b_kb  = ((lane >> 3) & 1) * 16;                     // + ks*32
    uint32_t a_off[4][4], b_off[4][4];                            // [ks][mi/nh]
#pragma unroll
    for (int ks = 0; ks < 4; ks++) {
#pragma unroll
        for (int mi = 0; mi < 4; mi++)
            a_off[ks][mi] = (uint32_t)((a_row + mi * 16) * PITCH + ks * 32 + a_kb);
#pragma unroll
        for (int nh = 0; nh < 4; nh++)
            b_off[ks][nh] = (uint32_t)((b_row + nh * 16) * PITCH + ks * 32 + b_kb);
    }

    uint32_t afr[2][4][4], bfr[2][4][4];   // double-buffered fragments

    auto ld_frags = [&](int pb, int ks, uint32_t sa, uint32_t sB) {
#pragma unroll
        for (int mi = 0; mi < 4; mi++) ldsm_x4(afr[pb][mi], sa + a_off[ks][mi]);
#pragma unroll
        for (int nh = 0; nh < 4; nh++) ldsm_x4(bfr[pb][nh], sB + b_off[ks][nh]);
    };
    auto do_mmas = [&](int pb) {
#pragma unroll
        for (int mi = 0; mi < 4; mi++)
#pragma unroll
            for (int ni = 0; ni < 8; ni++)
                mma_bf16(acc[mi][ni], afr[pb][mi], &bfr[pb][ni >> 1][(ni & 1) * 2]);
    };

    for (int i = 0; i < NIT; i++) {
        mbar_wait(sb + 8u * (uint32_t)(i % 3), (i / 3) & 1);  // chunk i resident
        __syncthreads();   // all warps finished iter i-1 (WAR for stage reuse)

        const uint32_t sa = sb + SMEM_DATA_OFF + (uint32_t)(i % 3) * STAGE_BYTES;
        const uint32_t sB = sa + A_STAGE_BYTES;

        ld_frags(0, 0, sa, sB);          // exposed load for ks=0

        if (i + 2 < NIT) {
            int s2 = (i + 2) % 3;
            if (tid == 0) mbar_expect_tx(sb + 8u * (uint32_t)s2, STAGE_TX);
            issue_loads(s2, i + 2);
        }

#pragma unroll
        for (int ks = 0; ks < 4; ks++) {
            if (ks < 3) ld_frags((ks + 1) & 1, ks + 1, sa, sB);  // prefetch
            do_mmas(ks & 1);
        }
    }

    // Epilogue: c0,c1 -> (row = lane/4, col = (lane&3)*2), c2,c3 -> row+8.
    const float* bb = bias + bn + wn * 64;
#pragma unroll
    for (int ni = 0; ni < 8; ni++) {
        int col = ni * 8 + (lane & 3) * 2;
        float b0 = bb[col], b1 = bb[col + 1];
#pragma unroll
        for (int mi = 0; mi < 4; mi++) {
            int row = bm + wm * 64 + mi * 16 + (lane >> 2);
            float* p = out + (size_t)row * NDIM + bn + wn * 64 + col;
            float2 v0; v0.x = acc[mi][ni][0] + b0; v0.y = acc[mi][ni][1] + b1;
            *reinterpret_cast<float2*>(p) = v0;
            float2 v1; v1.x = acc[mi][ni][2] + b0; v1.y = acc[mi][ni][3] + b1;
            *reinterpret_cast<float2*>(p + (size_t)8 * NDIM) = v1;
        }
    }
}

// ---------------------------------------------------------------------------
// Host entry
// ---------------------------------------------------------------------------
extern "C" void kernel_launch(void* const* d_in, const int* in_sizes, int n_in,
                              void* d_out, int out_size)
{
    const float* x       = (const float*)d_in[0];
    const float* scales  = (const float*)d_in[1];
    const float* bias    = (const float*)d_in[2];
    const int*   qweight = (const int*)d_in[3];
    float* out = (float*)d_out;
    (void)in_sizes; (void)n_in; (void)out_size;

    convx_kernel<<<(int)((size_t)MDIM * KDIM / (256 * 8)), 256>>>(x);
    dequant_kernel<<<(NDIM * 512) / 256, 256>>>(qweight, scales);

    cudaFuncSetAttribute(gemm_kernel,
                         cudaFuncAttributeMaxDynamicSharedMemorySize, SMEM_BYTES);
    dim3 grid(NDIM / BN, MDIM / BM);   // x = n-tiles: W^T stays L2-resident
    gemm_kernel<<<grid, 128, SMEM_BYTES>>>(out, bias);
}

// round 8
// speedup vs baseline: 1.7362x; 1.7362x over previous
#include <cuda_runtime.h>
#include <cuda_bf16.h>
#include <cstdint>
#include <cstddef>

// ---------------------------------------------------------------------------
// Problem dims (fixed by the dataset)
// ---------------------------------------------------------------------------
#define MDIM 8192
#define NDIM 4096
#define KDIM 4096

#define BM 128
#define BN 256
#define BK 128
#define NIT (KDIM / BK)          // 32
#define A_PART 32768             // 2 sub-chunks x (128 rows x 128B)
#define B_PART 65536             // 2 sub-chunks x (256 rows x 128B)
#define STAGE_BYTES (A_PART + B_PART)       // 98304
#define SMEM_BYTES (2 * STAGE_BYTES)        // 196608

// ---------------------------------------------------------------------------
// Scratch (device globals: the sanctioned no-alloc workaround)
// ---------------------------------------------------------------------------
__device__ __nv_bfloat16 g_A[(size_t)MDIM * KDIM];   // x as bf16, [M,K] row-major
__device__ __nv_bfloat16 g_Wt[(size_t)NDIM * KDIM];  // dequant W^T, [N,K] row-major

__constant__ float c_nf4[16] = {
    -1.0f, -0.6961928009986877f, -0.5250730514526367f, -0.39491748809814453f,
    -0.28444138169288635f, -0.18477343022823334f, -0.09105003625154495f, 0.0f,
    0.07958029955625534f, 0.16093020141124725f, 0.24611230194568634f,
    0.33791524171829224f, 0.44070982933044434f, 0.5626170039176941f,
    0.7229568362236023f, 1.0f };

// ---------------------------------------------------------------------------
// PTX helpers (baseline sm_80 features only — NO 'a'-suffix features)
// ---------------------------------------------------------------------------
static __device__ __forceinline__ uint32_t s2u(const void* p) {
    uint32_t a;
    asm("{ .reg .u64 t; cvta.to.shared.u64 t, %1; cvt.u32.u64 %0, t; }"
        : "=r"(a) : "l"(p));
    return a;
}
static __device__ __forceinline__ void cp16(uint32_t dst, const void* src) {
    asm volatile("cp.async.cg.shared.global [%0], [%1], 16;"
                 :: "r"(dst), "l"(src) : "memory");
}
static __device__ __forceinline__ void cp_commit() {
    asm volatile("cp.async.commit_group;" ::: "memory");
}
static __device__ __forceinline__ void cp_wait0() {
    asm volatile("cp.async.wait_group 0;" ::: "memory");
}
static __device__ __forceinline__ void ldsm_x4(uint32_t* r, uint32_t addr) {
    asm volatile("ldmatrix.sync.aligned.m8n8.x4.shared.b16 {%0,%1,%2,%3}, [%4];"
                 : "=r"(r[0]), "=r"(r[1]), "=r"(r[2]), "=r"(r[3])
                 : "r"(addr));
}
static __device__ __forceinline__ void mma_bf16(
    float* d, const uint32_t* a, const uint32_t* b)
{
    asm volatile(
        "mma.sync.aligned.m16n8k16.row.col.f32.bf16.bf16.f32 "
        "{%0,%1,%2,%3}, {%4,%5,%6,%7}, {%8,%9}, {%0,%1,%2,%3};"
        : "+f"(d[0]), "+f"(d[1]), "+f"(d[2]), "+f"(d[3])
        : "r"(a[0]), "r"(a[1]), "r"(a[2]), "r"(a[3]), "r"(b[0]), "r"(b[1]));
}
static __device__ __forceinline__ uint32_t sw128(uint32_t off) {
    return off ^ ((off >> 3) & 0x70);
}

// ---------------------------------------------------------------------------
// Kernel 1: fused prologue.
//   Blocks [0, 16384): x (fp32) -> g_A (bf16)
//   Blocks [16384, 24576): NF4 dequant+transpose qweight -> g_Wt (bf16 [N,K])
// ---------------------------------------------------------------------------
__global__ void __launch_bounds__(256) prep_kernel(
    const float* __restrict__ x,
    const int* __restrict__ qw, const float* __restrict__ sc)
{
    int b = blockIdx.x;
    if (b < 16384) {
        size_t i = ((size_t)b * 256 + threadIdx.x) * 8;
        float4 a = *reinterpret_cast<const float4*>(x + i);
        float4 c = *reinterpret_cast<const float4*>(x + i + 4);
        __nv_bfloat162 h0 = __floats2bfloat162_rn(a.x, a.y);
        __nv_bfloat162 h1 = __floats2bfloat162_rn(a.z, a.w);
        __nv_bfloat162 h2 = __floats2bfloat162_rn(c.x, c.y);
        __nv_bfloat162 h3 = __floats2bfloat162_rn(c.z, c.w);
        uint4 u;
        u.x = *reinterpret_cast<unsigned*>(&h0);
        u.y = *reinterpret_cast<unsigned*>(&h1);
        u.z = *reinterpret_cast<unsigned*>(&h2);
        u.w = *reinterpret_cast<unsigned*>(&h3);
        *reinterpret_cast<uint4*>(&g_A[i]) = u;
    } else {
        int idx = (b - 16384) * 256 + threadIdx.x;   // 0 .. N*512-1
        int n = idx >> 9;                            // output column (0..4095)
        int r = idx & 511;                           // int32 row (k = 8r + j)
        unsigned q = (unsigned)qw[(size_t)r * NDIM + n];
        float s = sc[(size_t)(r >> 4) * NDIM + n];   // group = r/16
        unsigned w[4];
#pragma unroll
        for (int jj = 0; jj < 4; jj++) {
            float f0 = c_nf4[(q >> (8 * jj)) & 15] * s;
            float f1 = c_nf4[(q >> (8 * jj + 4)) & 15] * s;
            __nv_bfloat162 h = __floats2bfloat162_rn(f0, f1);
            w[jj] = *reinterpret_cast<unsigned*>(&h);
        }
        uint4 u; u.x = w[0]; u.y = w[1]; u.z = w[2]; u.w = w[3];
        *reinterpret_cast<uint4*>(&g_Wt[(size_t)n * KDIM + r * 8]) = u;
    }
}

// ---------------------------------------------------------------------------
// Kernel 2: GEMM  out[M,N] = g_A[M,K] @ g_Wt[N,K]^T + bias
//   128x256 CTA tile, 8 warps 2(M)x4(N), warp tile 64x64, BK=128 chunks
//   (stored as 2 sub-chunks of 128B rows, SW128 swizzled), 2-stage cp.async
//   double buffer (192 KB smem), register double-buffered fragments.
// ---------------------------------------------------------------------------
__global__ void __launch_bounds__(256, 1) gemm_kernel(
    float* __restrict__ out, const float* __restrict__ bias)
{
    extern __shared__ char smem[];
    const uint32_t sb = s2u(smem);
    const int tid = threadIdx.x;
    const int wid = tid >> 5, lane = tid & 31;
    const int wm = wid >> 2, wn = wid & 3;        // warp grid 2 (M) x 4 (N)
    const int bm = blockIdx.y * BM, bn = blockIdx.x * BN;

    const char* Ag = (const char*)(g_A  + (size_t)bm * KDIM);
    const char* Bg = (const char*)(g_Wt + (size_t)bn * KDIM);

    // Load one K-chunk (kc, 256B per row) of A+B into stage s.
    auto load_stage = [&](int s, int kc) {
        const uint32_t sa = sb + (uint32_t)s * STAGE_BYTES;
        const uint32_t sB = sa + A_PART;
#pragma unroll
        for (int kk = 0; kk < 2; kk++) {
            const char* a0 = Ag + (size_t)kc * 256 + kk * 128;
            const char* b0 = Bg + (size_t)kc * 256 + kk * 128;
#pragma unroll
            for (int t = 0; t < 4; t++) {          // A: 1024 x 16B per sub
                int c = tid + t * 256;
                int row = c >> 3;                  // 0..127
                int kb = (c & 7) * 16;
                cp16(sa + kk * 16384 + sw128((uint32_t)(row * 128 + kb)),
                     a0 + (size_t)row * (KDIM * 2) + kb);
            }
#pragma unroll
            for (int t = 0; t < 8; t++) {          // B: 2048 x 16B per sub
                int c = tid + t * 256;
                int row = c >> 3;                  // 0..255
                int kb = (c & 7) * 16;
                cp16(sB + kk * 32768 + sw128((uint32_t)(row * 128 + kb)),
                     b0 + (size_t)row * (KDIM * 2) + kb);
            }
        }
        cp_commit();
    };

    // Prologue: stage 0
    load_stage(0, 0);

    float acc[4][8][4];
#pragma unroll
    for (int mi = 0; mi < 4; mi++)
#pragma unroll
        for (int ni = 0; ni < 8; ni++)
#pragma unroll
            for (int j = 0; j < 4; j++) acc[mi][ni][j] = 0.0f;

    // Per-thread ldmatrix swizzled offsets within a 128-row x 128B sub-chunk.
    const int a_row = wm * 64 + (lane & 15);                      // + mi*16
    const int a_kb  = ((lane >> 4) & 1) * 16;                     // + k4*32
    const int b_row = wn * 64 + (lane & 7) + ((lane >> 4) << 3);  // + nh*16
    const int b_kb  = ((lane >> 3) & 1) * 16;                     // + k4*32
    uint32_t a_off[4][4], b_off[4][4];                            // [k4][mi/nh]
#pragma unroll
    for (int k4 = 0; k4 < 4; k4++) {
#pragma unroll
        for (int mi = 0; mi < 4; mi++)
            a_off[k4][mi] = sw128((uint32_t)((a_row + mi * 16) * 128 + k4 * 32 + a_kb));
#pragma unroll
        for (int nh = 0; nh < 4; nh++)
            b_off[k4][nh] = sw128((uint32_t)((b_row + nh * 16) * 128 + k4 * 32 + b_kb));
    }

    uint32_t afr[2][4][4], bfr[2][4][4];   // double-buffered fragments

    // Load fragments for k-step ks (0..7) of the stage at (sa, sB) into pb.
    auto ld_frags = [&](int pb, int ks, uint32_t sa, uint32_t sB) {
        const uint32_t sak = sa + (uint32_t)(ks >> 2) * 16384;
        const uint32_t sBk = sB + (uint32_t)(ks >> 2) * 32768;
        const int k4 = ks & 3;
#pragma unroll
        for (int mi = 0; mi < 4; mi++) ldsm_x4(afr[pb][mi], sak + a_off[k4][mi]);
#pragma unroll
        for (int nh = 0; nh < 4; nh++) ldsm_x4(bfr[pb][nh], sBk + b_off[k4][nh]);
    };
    auto do_mmas = [&](int pb) {
#pragma unroll
        for (int mi = 0; mi < 4; mi++)
#pragma unroll
            for (int ni = 0; ni < 8; ni++)
                mma_bf16(acc[mi][ni], afr[pb][mi], &bfr[pb][ni >> 1][(ni & 1) * 2]);
    };

    for (int i = 0; i < NIT; i++) {
        cp_wait0();            // chunk i resident (this thread's copies)
        __syncthreads();       // all threads waited -> full stage visible; and
                               // all warps done reading stage (i+1)&1 (WAR)
        const uint32_t sa = sb + (uint32_t)(i & 1) * STAGE_BYTES;
        const uint32_t sB = sa + A_PART;

        ld_frags(0, 0, sa, sB);          // exposed load for ks=0

        if (i + 1 < NIT) load_stage((i + 1) & 1, i + 1);

#pragma unroll
        for (int ks = 0; ks < 8; ks++) {
            if (ks < 7) ld_frags((ks + 1) & 1, ks + 1, sa, sB);  // prefetch
            do_mmas(ks & 1);
        }
    }

    // Epilogue: c0,c1 -> (row = lane/4, col = (lane&3)*2), c2,c3 -> row+8.
    const float* bb = bias + bn + wn * 64;
#pragma unroll
    for (int ni = 0; ni < 8; ni++) {
        int col = ni * 8 + (lane & 3) * 2;
        float b0 = bb[col], b1 = bb[col + 1];
#pragma unroll
        for (int mi = 0; mi < 4; mi++) {
            int row = bm + wm * 64 + mi * 16 + (lane >> 2);
            float* p = out + (size_t)row * NDIM + bn + wn * 64 + col;
            float2 v0; v0.x = acc[mi][ni][0] + b0; v0.y = acc[mi][ni][1] + b1;
            *reinterpret_cast<float2*>(p) = v0;
            float2 v1; v1.x = acc[mi][ni][2] + b0; v1.y = acc[mi][ni][3] + b1;
            *reinterpret_cast<float2*>(p + (size_t)8 * NDIM) = v1;
        }
    }
}

// ---------------------------------------------------------------------------
// Host entry
// ---------------------------------------------------------------------------
extern "C" void kernel_launch(void* const* d_in, const int* in_sizes, int n_in,
                              void* d_out, int out_size)
{
    const float* x       = (const float*)d_in[0];
    const float* scales  = (const float*)d_in[1];
    const float* bias    = (const float*)d_in[2];
    const int*   qweight = (const int*)d_in[3];
    float* out = (float*)d_out;
    (void)in_sizes; (void)n_in; (void)out_size;

    // Fused prologue: 16384 convx blocks + 8192 dequant blocks.
    prep_kernel<<<16384 + 8192, 256>>>(x, qweight, scales);

    cudaFuncSetAttribute(gemm_kernel,
                         cudaFuncAttributeMaxDynamicSharedMemorySize, SMEM_BYTES);
    dim3 grid(NDIM / BN, MDIM / BM);   // (16, 64); x = n-tiles for L2 reuse
    gemm_kernel<<<grid, 256, SMEM_BYTES>>>(out, bias);
}

// round 9
// speedup vs baseline: 1.7969x; 1.0350x over previous
#include <cuda_runtime.h>
#include <cuda_bf16.h>
#include <cstdint>
#include <cstddef>

// ---------------------------------------------------------------------------
// Problem dims (fixed by the dataset)
// ---------------------------------------------------------------------------
#define MDIM 8192
#define NDIM 4096
#define KDIM 4096

#define BM 128
#define BN 128
#define BK 64
#define NSTAGE 3
#define NIT (KDIM / BK)          // 64
#define A_STAGE_BYTES 16384      // 128 rows * 128 B
#define STAGE_BYTES 32768        // A + B
#define SMEM_BYTES (NSTAGE * STAGE_BYTES)   // 98304 -> 2 CTAs/SM

// ---------------------------------------------------------------------------
// Scratch (device globals: the sanctioned no-alloc workaround)
// ---------------------------------------------------------------------------
__device__ __nv_bfloat16 g_A[(size_t)MDIM * KDIM];   // x as bf16, [M,K] row-major
__device__ __nv_bfloat16 g_Wt[(size_t)NDIM * KDIM];  // dequant W^T, [N,K] row-major

__constant__ float c_nf4[16] = {
    -1.0f, -0.6961928009986877f, -0.5250730514526367f, -0.39491748809814453f,
    -0.28444138169288635f, -0.18477343022823334f, -0.09105003625154495f, 0.0f,
    0.07958029955625534f, 0.16093020141124725f, 0.24611230194568634f,
    0.33791524171829224f, 0.44070982933044434f, 0.5626170039176941f,
    0.7229568362236023f, 1.0f };

// ---------------------------------------------------------------------------
// PTX helpers (baseline sm_80 features only — NO 'a'-suffix features)
// ---------------------------------------------------------------------------
static __device__ __forceinline__ uint32_t s2u(const void* p) {
    uint32_t a;
    asm("{ .reg .u64 t; cvta.to.shared.u64 t, %1; cvt.u32.u64 %0, t; }"
        : "=r"(a) : "l"(p));
    return a;
}
static __device__ __forceinline__ void cp16(uint32_t dst, const void* src) {
    asm volatile("cp.async.cg.shared.global [%0], [%1], 16;"
                 :: "r"(dst), "l"(src) : "memory");
}
static __device__ __forceinline__ void cp_commit() {
    asm volatile("cp.async.commit_group;" ::: "memory");
}
static __device__ __forceinline__ void cp_wait1() {
    asm volatile("cp.async.wait_group 1;" ::: "memory");
}
static __device__ __forceinline__ void ldsm_x4(uint32_t* r, uint32_t addr) {
    asm volatile("ldmatrix.sync.aligned.m8n8.x4.shared.b16 {%0,%1,%2,%3}, [%4];"
                 : "=r"(r[0]), "=r"(r[1]), "=r"(r[2]), "=r"(r[3])
                 : "r"(addr));
}
static __device__ __forceinline__ void mma_bf16(
    float* d, const uint32_t* a, const uint32_t* b)
{
    asm volatile(
        "mma.sync.aligned.m16n8k16.row.col.f32.bf16.bf16.f32 "
        "{%0,%1,%2,%3}, {%4,%5,%6,%7}, {%8,%9}, {%0,%1,%2,%3};"
        : "+f"(d[0]), "+f"(d[1]), "+f"(d[2]), "+f"(d[3])
        : "r"(a[0]), "r"(a[1]), "r"(a[2]), "r"(a[3]), "r"(b[0]), "r"(b[1]));
}
static __device__ __forceinline__ uint32_t sw128(uint32_t off) {
    return off ^ ((off >> 3) & 0x70);
}

// ---------------------------------------------------------------------------
// Kernel 1: fused prologue.
//   Blocks [0, 16384): x (fp32) -> g_A (bf16)
//   Blocks [16384, 24576): NF4 dequant+transpose qweight -> g_Wt (bf16 [N,K])
// ---------------------------------------------------------------------------
__global__ void __launch_bounds__(256) prep_kernel(
    const float* __restrict__ x,
    const int* __restrict__ qw, const float* __restrict__ sc)
{
    int b = blockIdx.x;
    if (b < 16384) {
        size_t i = ((size_t)b * 256 + threadIdx.x) * 8;
        float4 a = *reinterpret_cast<const float4*>(x + i);
        float4 c = *reinterpret_cast<const float4*>(x + i + 4);
        __nv_bfloat162 h0 = __floats2bfloat162_rn(a.x, a.y);
        __nv_bfloat162 h1 = __floats2bfloat162_rn(a.z, a.w);
        __nv_bfloat162 h2 = __floats2bfloat162_rn(c.x, c.y);
        __nv_bfloat162 h3 = __floats2bfloat162_rn(c.z, c.w);
        uint4 u;
        u.x = *reinterpret_cast<unsigned*>(&h0);
        u.y = *reinterpret_cast<unsigned*>(&h1);
        u.z = *reinterpret_cast<unsigned*>(&h2);
        u.w = *reinterpret_cast<unsigned*>(&h3);
        *reinterpret_cast<uint4*>(&g_A[i]) = u;
    } else {
        int idx = (b - 16384) * 256 + threadIdx.x;   // 0 .. N*512-1
        int n = idx >> 9;                            // output column (0..4095)
        int r = idx & 511;                           // int32 row (k = 8r + j)
        unsigned q = (unsigned)qw[(size_t)r * NDIM + n];
        float s = sc[(size_t)(r >> 4) * NDIM + n];   // group = r/16
        unsigned w[4];
#pragma unroll
        for (int jj = 0; jj < 4; jj++) {
            float f0 = c_nf4[(q >> (8 * jj)) & 15] * s;
            float f1 = c_nf4[(q >> (8 * jj + 4)) & 15] * s;
            __nv_bfloat162 h = __floats2bfloat162_rn(f0, f1);
            w[jj] = *reinterpret_cast<unsigned*>(&h);
        }
        uint4 u; u.x = w[0]; u.y = w[1]; u.z = w[2]; u.w = w[3];
        *reinterpret_cast<uint4*>(&g_Wt[(size_t)n * KDIM + r * 8]) = u;
    }
}

// ---------------------------------------------------------------------------
// Kernel 2: GEMM  out[M,N] = g_A[M,K] @ g_Wt[N,K]^T + bias
//   128x128 CTA tile, 8 warps in 2(M) x 4(N), warp tile 64x32,
//   3-stage cp.async pipeline (96 KB -> 2 CTAs/SM = 16 warps = 4/SMSP),
//   SW128 swizzle, single-buffered fragments (occupancy hides latency).
// ---------------------------------------------------------------------------
__global__ void __launch_bounds__(256, 2) gemm_kernel(
    float* __restrict__ out, const float* __restrict__ bias)
{
    extern __shared__ char smem[];
    const uint32_t sb = s2u(smem);
    const int tid = threadIdx.x;
    const int wid = tid >> 5, lane = tid & 31;
    const int wm = wid >> 2, wn = wid & 3;        // warp grid 2 (M) x 4 (N)
    const int bm = blockIdx.y * BM, bn = blockIdx.x * BN;

    const char* Ag = (const char*)(g_A  + (size_t)bm * KDIM);
    const char* Bg = (const char*)(g_Wt + (size_t)bn * KDIM);

    // Load one K-chunk (kc) of A+B into stage s. 2048 x 16B, 8/thread.
    auto load_stage = [&](int s, int kc) {
        const uint32_t sa = sb + (uint32_t)s * STAGE_BYTES;
        const uint32_t sB = sa + A_STAGE_BYTES;
        const char* a0 = Ag + (size_t)kc * 128;
        const char* b0 = Bg + (size_t)kc * 128;
#pragma unroll
        for (int t = 0; t < 4; t++) {              // A: 1024 x 16B
            int c = tid + t * 256;
            int row = c >> 3;                      // 0..127
            int kb = (c & 7) * 16;
            cp16(sa + sw128((uint32_t)(row * 128 + kb)),
                 a0 + (size_t)row * (KDIM * 2) + kb);
        }
#pragma unroll
        for (int t = 0; t < 4; t++) {              // B: 1024 x 16B
            int c = tid + t * 256;
            int row = c >> 3;                      // 0..127
            int kb = (c & 7) * 16;
            cp16(sB + sw128((uint32_t)(row * 128 + kb)),
                 b0 + (size_t)row * (KDIM * 2) + kb);
        }
        cp_commit();
    };

    // Prologue: fill stages 0..1
    load_stage(0, 0);
    load_stage(1, 1);

    float acc[4][4][4];
#pragma unroll
    for (int mi = 0; mi < 4; mi++)
#pragma unroll
        for (int ni = 0; ni < 4; ni++)
#pragma unroll
            for (int j = 0; j < 4; j++) acc[mi][ni][j] = 0.0f;

    // Per-thread ldmatrix row/col components (offsets computed inline to
    // minimize register footprint; occupancy hides the ALU cost).
    const int a_row = wm * 64 + (lane & 15);                      // + mi*16
    const int a_kb  = ((lane >> 4) & 1) * 16;                     // + ks*32
    const int b_row = wn * 32 + (lane & 7) + ((lane >> 4) << 3);  // + nh*16
    const int b_kb  = ((lane >> 3) & 1) * 16;                     // + ks*32

    for (int i = 0; i < NIT; i++) {
        cp_wait1();            // stage i resident
        __syncthreads();

        if (i + 2 < NIT) load_stage((i + 2) % 3, i + 2);
        else             cp_commit();   // keep wait count aligned

        const uint32_t sa = sb + (uint32_t)(i % 3) * STAGE_BYTES;
        const uint32_t sB = sa + A_STAGE_BYTES;

#pragma unroll
        for (int ks = 0; ks < 4; ks++) {
            uint32_t afr[4][4], bfr[2][4];
#pragma unroll
            for (int mi = 0; mi < 4; mi++) {
                uint32_t off = (uint32_t)((a_row + mi * 16) * 128 + ks * 32 + a_kb);
                ldsm_x4(afr[mi], sa + sw128(off));
            }
#pragma unroll
            for (int nh = 0; nh < 2; nh++) {
                uint32_t off = (uint32_t)((b_row + nh * 16) * 128 + ks * 32 + b_kb);
                ldsm_x4(bfr[nh], sB + sw128(off));
            }
#pragma unroll
            for (int mi = 0; mi < 4; mi++)
#pragma unroll
                for (int ni = 0; ni < 4; ni++)
                    mma_bf16(acc[mi][ni], afr[mi], &bfr[ni >> 1][(ni & 1) * 2]);
        }
    }

    // Epilogue: c0,c1 -> (row = lane/4, col = (lane&3)*2), c2,c3 -> row+8.
    const float* bb = bias + bn + wn * 32;
#pragma unroll
    for (int ni = 0; ni < 4; ni++) {
        int col = ni * 8 + (lane & 3) * 2;
        float b0 = bb[col], b1 = bb[col + 1];
#pragma unroll
        for (int mi = 0; mi < 4; mi++) {
            int row = bm + wm * 64 + mi * 16 + (lane >> 2);
            float* p = out + (size_t)row * NDIM + bn + wn * 32 + col;
            float2 v0; v0.x = acc[mi][ni][0] + b0; v0.y = acc[mi][ni][1] + b1;
            *reinterpret_cast<float2*>(p) = v0;
            float2 v1; v1.x = acc[mi][ni][2] + b0; v1.y = acc[mi][ni][3] + b1;
            *reinterpret_cast<float2*>(p + (size_t)8 * NDIM) = v1;
        }
    }
}

// ---------------------------------------------------------------------------
// Host entry
// ---------------------------------------------------------------------------
extern "C" void kernel_launch(void* const* d_in, const int* in_sizes, int n_in,
                              void* d_out, int out_size)
{
    const float* x       = (const float*)d_in[0];
    const float* scales  = (const float*)d_in[1];
    const float* bias    = (const float*)d_in[2];
    const int*   qweight = (const int*)d_in[3];
    float* out = (float*)d_out;
    (void)in_sizes; (void)n_in; (void)out_size;

    // Fused prologue: 16384 convx blocks + 8192 dequant blocks.
    prep_kernel<<<16384 + 8192, 256>>>(x, qweight, scales);

    cudaFuncSetAttribute(gemm_kernel,
                         cudaFuncAttributeMaxDynamicSharedMemorySize, SMEM_BYTES);
    dim3 grid(NDIM / BN, MDIM / BM);   // (32, 64); x = n-tiles for L2 reuse
    gemm_kernel<<<grid, 256, SMEM_BYTES>>>(out, bias);
}

// round 10
// speedup vs baseline: 1.9745x; 1.0988x over previous
#include <cuda_runtime.h>
#include <cuda_bf16.h>
#include <cstdint>
#include <cstddef>

// ---------------------------------------------------------------------------
// Problem dims (fixed by the dataset)
// ---------------------------------------------------------------------------
#define MDIM 8192
#define NDIM 4096
#define KDIM 4096

#define BM 128
#define BN 128
#define BK 64
#define NSTAGE 3
#define NIT (KDIM / BK)          // 64
#define A_STAGE_BYTES 16384      // 128 rows * 128 B
#define B_STAGE_BYTES 16384      // 128 rows * 128 B
#define STAGE_BYTES (A_STAGE_BYTES + B_STAGE_BYTES)   // 32768
#define SMEM_BYTES (NSTAGE * STAGE_BYTES)             // 98304 -> 2 CTAs/SM

// ---------------------------------------------------------------------------
// Scratch (device globals: the sanctioned no-alloc workaround)
// ---------------------------------------------------------------------------
__device__ __nv_bfloat16 g_A[(size_t)MDIM * KDIM];   // x as bf16, [M,K] row-major
__device__ __nv_bfloat16 g_Wt[(size_t)NDIM * KDIM];  // dequant W^T, [N,K] row-major

__constant__ float c_nf4[16] = {
    -1.0f, -0.6961928009986877f, -0.5250730514526367f, -0.39491748809814453f,
    -0.28444138169288635f, -0.18477343022823334f, -0.09105003625154495f, 0.0f,
    0.07958029955625534f, 0.16093020141124725f, 0.24611230194568634f,
    0.33791524171829224f, 0.44070982933044434f, 0.5626170039176941f,
    0.7229568362236023f, 1.0f };

// ---------------------------------------------------------------------------
// PTX helpers (baseline sm_80 features only — NO 'a'-suffix features)
// ---------------------------------------------------------------------------
static __device__ __forceinline__ uint32_t s2u(const void* p) {
    uint32_t a;
    asm("{ .reg .u64 t; cvta.to.shared.u64 t, %1; cvt.u32.u64 %0, t; }"
        : "=r"(a) : "l"(p));
    return a;
}
static __device__ __forceinline__ void cp16(uint32_t dst, const void* src) {
    asm volatile("cp.async.cg.shared.global [%0], [%1], 16;"
                 :: "r"(dst), "l"(src) : "memory");
}
static __device__ __forceinline__ void cp_commit() {
    asm volatile("cp.async.commit_group;" ::: "memory");
}
static __device__ __forceinline__ void cp_wait1() {
    asm volatile("cp.async.wait_group 1;" ::: "memory");
}
static __device__ __forceinline__ void ldsm_x4(uint32_t* r, uint32_t addr) {
    asm volatile("ldmatrix.sync.aligned.m8n8.x4.shared.b16 {%0,%1,%2,%3}, [%4];"
                 : "=r"(r[0]), "=r"(r[1]), "=r"(r[2]), "=r"(r[3])
                 : "r"(addr));
}
static __device__ __forceinline__ void mma_bf16(
    float* d, const uint32_t* a, const uint32_t* b)
{
    asm volatile(
        "mma.sync.aligned.m16n8k16.row.col.f32.bf16.bf16.f32 "
        "{%0,%1,%2,%3}, {%4,%5,%6,%7}, {%8,%9}, {%0,%1,%2,%3};"
        : "+f"(d[0]), "+f"(d[1]), "+f"(d[2]), "+f"(d[3])
        : "r"(a[0]), "r"(a[1]), "r"(a[2]), "r"(a[3]), "r"(b[0]), "r"(b[1]));
}
static __device__ __forceinline__ uint32_t sw128(uint32_t off) {
    return off ^ ((off >> 3) & 0x70);
}

// ---------------------------------------------------------------------------
// Kernel 1: fused prologue.
//   Blocks [0, 16384): x (fp32) -> g_A (bf16)
//   Blocks [16384, 24576): NF4 dequant+transpose qweight -> g_Wt (bf16 [N,K])
// ---------------------------------------------------------------------------
__global__ void __launch_bounds__(256) prep_kernel(
    const float* __restrict__ x,
    const int* __restrict__ qw, const float* __restrict__ sc)
{
    int b = blockIdx.x;
    if (b < 16384) {
        size_t i = ((size_t)b * 256 + threadIdx.x) * 8;
        float4 a = *reinterpret_cast<const float4*>(x + i);
        float4 c = *reinterpret_cast<const float4*>(x + i + 4);
        __nv_bfloat162 h0 = __floats2bfloat162_rn(a.x, a.y);
        __nv_bfloat162 h1 = __floats2bfloat162_rn(a.z, a.w);
        __nv_bfloat162 h2 = __floats2bfloat162_rn(c.x, c.y);
        __nv_bfloat162 h3 = __floats2bfloat162_rn(c.z, c.w);
        uint4 u;
        u.x = *reinterpret_cast<unsigned*>(&h0);
        u.y = *reinterpret_cast<unsigned*>(&h1);
        u.z = *reinterpret_cast<unsigned*>(&h2);
        u.w = *reinterpret_cast<unsigned*>(&h3);
        *reinterpret_cast<uint4*>(&g_A[i]) = u;
    } else {
        int idx = (b - 16384) * 256 + threadIdx.x;   // 0 .. N*512-1
        int n = idx >> 9;                            // output column (0..4095)
        int r = idx & 511;                           // int32 row (k = 8r + j)
        unsigned q = (unsigned)qw[(size_t)r * NDIM + n];
        float s = sc[(size_t)(r >> 4) * NDIM + n];   // group = r/16
        unsigned w[4];
#pragma unroll
        for (int jj = 0; jj < 4; jj++) {
            float f0 = c_nf4[(q >> (8 * jj)) & 15] * s;
            float f1 = c_nf4[(q >> (8 * jj + 4)) & 15] * s;
            __nv_bfloat162 h = __floats2bfloat162_rn(f0, f1);
            w[jj] = *reinterpret_cast<unsigned*>(&h);
        }
        uint4 u; u.x = w[0]; u.y = w[1]; u.z = w[2]; u.w = w[3];
        *reinterpret_cast<uint4*>(&g_Wt[(size_t)n * KDIM + r * 8]) = u;
    }
}

// ---------------------------------------------------------------------------
// Kernel 2: GEMM  out[M,N] = g_A[M,K] @ g_Wt[N,K]^T + bias
//   (Best-measured config = R6.) 128x128 CTA tile, 4 warps 2x2, warp tile
//   64x64, 3-stage cp.async pipeline (96 KB -> 2 CTAs/SM), SW128 swizzle,
//   register double-buffered fragments: ldsm for k-step ks+1 issues before
//   the 32 MMAs of ks.
// ---------------------------------------------------------------------------
__global__ void __launch_bounds__(128, 2) gemm_kernel(
    float* __restrict__ out, const float* __restrict__ bias)
{
    extern __shared__ char smem[];
    const uint32_t sb = s2u(smem);
    const int tid = threadIdx.x;
    const int wid = tid >> 5, lane = tid & 31;
    const int wm = wid >> 1, wn = wid & 1;        // warp grid 2 (M) x 2 (N)
    const int bm = blockIdx.y * BM, bn = blockIdx.x * BN;

    const char* Ag = (const char*)(g_A  + (size_t)bm * KDIM);
    const char* Bg = (const char*)(g_Wt + (size_t)bn * KDIM);

    // Load one K-chunk (kc) of A+B into stage s. 2048 x 16B, 16/thread.
    auto load_stage = [&](int s, int kc) {
        const uint32_t sa = sb + (uint32_t)s * STAGE_BYTES;
        const uint32_t sB = sa + A_STAGE_BYTES;
        const char* a0 = Ag + (size_t)kc * 128;
        const char* b0 = Bg + (size_t)kc * 128;
#pragma unroll
        for (int t = 0; t < 8; t++) {              // A: 1024 x 16B
            int c = tid + t * 128;
            int row = c >> 3;
            int kb = (c & 7) * 16;
            cp16(sa + sw128((uint32_t)(row * 128 + kb)),
                 a0 + (size_t)row * (KDIM * 2) + kb);
        }
#pragma unroll
        for (int t = 0; t < 8; t++) {              // B: 1024 x 16B
            int c = tid + t * 128;
            int row = c >> 3;
            int kb = (c & 7) * 16;
            cp16(sB + sw128((uint32_t)(row * 128 + kb)),
                 b0 + (size_t)row * (KDIM * 2) + kb);
        }
        cp_commit();
    };

    // Prologue: fill stages 0..1
    load_stage(0, 0);
    load_stage(1, 1);

    float acc[4][8][4];
#pragma unroll
    for (int mi = 0; mi < 4; mi++)
#pragma unroll
        for (int ni = 0; ni < 8; ni++)
#pragma unroll
            for (int j = 0; j < 4; j++) acc[mi][ni][j] = 0.0f;

    // Per-thread ldmatrix swizzled offsets (stage-relative).
    const int a_row = wm * 64 + (lane & 15);                      // + mi*16
    const int a_kb  = ((lane >> 4) & 1) * 16;                     // + ks*32
    const int b_row = wn * 64 + (lane & 7) + ((lane >> 4) << 3);  // + nh*16
    const int b_kb  = ((lane >> 3) & 1) * 16;                     // + ks*32
    uint32_t a_off[4][4], b_off[4][4];                            // [ks][mi/nh]
#pragma unroll
    for (int ks = 0; ks < 4; ks++) {
#pragma unroll
        for (int mi = 0; mi < 4; mi++)
            a_off[ks][mi] = sw128((uint32_t)((a_row + mi * 16) * 128 + ks * 32 + a_kb));
#pragma unroll
        for (int nh = 0; nh < 4; nh++)
            b_off[ks][nh] = sw128((uint32_t)((b_row + nh * 16) * 128 + ks * 32 + b_kb));
    }

    uint32_t afr[2][4][4], bfr[2][4][4];   // double-buffered fragments

    auto ld_frags = [&](int pb, int ks, uint32_t sa, uint32_t sB) {
#pragma unroll
        for (int mi = 0; mi < 4; mi++) ldsm_x4(afr[pb][mi], sa + a_off[ks][mi]);
#pragma unroll
        for (int nh = 0; nh < 4; nh++) ldsm_x4(bfr[pb][nh], sB + b_off[ks][nh]);
    };
    auto do_mmas = [&](int pb) {
#pragma unroll
        for (int mi = 0; mi < 4; mi++)
#pragma unroll
            for (int ni = 0; ni < 8; ni++)
                mma_bf16(acc[mi][ni], afr[pb][mi], &bfr[pb][ni >> 1][(ni & 1) * 2]);
    };

    for (int i = 0; i < NIT; i++) {
        cp_wait1();            // stage i resident
        __syncthreads();

        const uint32_t sa = sb + (uint32_t)(i % 3) * STAGE_BYTES;
        const uint32_t sB = sa + A_STAGE_BYTES;

        ld_frags(0, 0, sa, sB);          // exposed load for ks=0

        if (i + 2 < NIT) load_stage((i + 2) % 3, i + 2);
        else             cp_commit();    // keep wait count aligned

#pragma unroll
        for (int ks = 0; ks < 4; ks++) {
            if (ks < 3) ld_frags((ks + 1) & 1, ks + 1, sa, sB);  // prefetch
            do_mmas(ks & 1);
        }
    }

    // Epilogue: c0,c1 -> (row = lane/4, col = (lane&3)*2), c2,c3 -> row+8.
    const float* bb = bias + bn + wn * 64;
#pragma unroll
    for (int ni = 0; ni < 8; ni++) {
        int col = ni * 8 + (lane & 3) * 2;
        float b0 = bb[col], b1 = bb[col + 1];
#pragma unroll
        for (int mi = 0; mi < 4; mi++) {
            int row = bm + wm * 64 + mi * 16 + (lane >> 2);
            float* p = out + (size_t)row * NDIM + bn + wn * 64 + col;
            float2 v0; v0.x = acc[mi][ni][0] + b0; v0.y = acc[mi][ni][1] + b1;
            *reinterpret_cast<float2*>(p) = v0;
            float2 v1; v1.x = acc[mi][ni][2] + b0; v1.y = acc[mi][ni][3] + b1;
            *reinterpret_cast<float2*>(p + (size_t)8 * NDIM) = v1;
        }
    }
}

// ---------------------------------------------------------------------------
// Host entry
// ---------------------------------------------------------------------------
extern "C" void kernel_launch(void* const* d_in, const int* in_sizes, int n_in,
                              void* d_out, int out_size)
{
    const float* x       = (const float*)d_in[0];
    const float* scales  = (const float*)d_in[1];
    const float* bias    = (const float*)d_in[2];
    const int*   qweight = (const int*)d_in[3];
    float* out = (float*)d_out;
    (void)in_sizes; (void)n_in; (void)out_size;

    // Fused prologue: 16384 convx blocks + 8192 dequant blocks.
    prep_kernel<<<16384 + 8192, 256>>>(x, qweight, scales);

    cudaFuncSetAttribute(gemm_kernel,
                         cudaFuncAttributeMaxDynamicSharedMemorySize, SMEM_BYTES);
    dim3 grid(NDIM / BN, MDIM / BM);   // (32, 64); x = n-tiles for L2 reuse
    gemm_kernel<<<grid, 128, SMEM_BYTES>>>(out, bias);
}